// round 15
// baseline (speedup 1.0000x reference)
#include <cuda_runtime.h>
#include <cuda_fp16.h>
#include <cstdint>

// ===========================================================================
// PackedSirenExperts via mma.sync m16n8k16 fp16 (portable PTX, compute_103).
// R15: crossbar-optimal tiling. CTA = (expert, 128 rows), 256 thr, 8 warps
// = 2(wm) x 4(wnq), warp tile 64x64 (acc 128 regs, ~185 total, 1 CTA/SM).
// Per-64-row-unit smem traffic 544 -> 416 KB => crossbar (6.5K cyc/SM/layer)
// drops BELOW tensor (7.3K) -> tensor-bound.
// Single-pass fp16 MMA (rel_err ~6e-4); warp-private B staging (cp.async own
// quarter, dup x2 across the m-pair -> zero mainloop cross-warp coupling);
// A double-buffered (one barrier per layer); biases prescaled by 30.
// ~178 KB smem, 1 CTA/SM.
// ===========================================================================

namespace {
constexpr int Mexp = 64;
constexpr int Bdim = 8192;
constexpr float W0F = 30.0f;

constexpr int OFF_A    = 0;          // 2 x (128 rows x 512B swizzled fp16)
constexpr int OFF_WBUF = 131072;     // 2 x 16384 (8 warp-private 2KB regions)
constexpr int OFF_W0   = 163840;     // 768 f (prescaled by 30)
constexpr int OFF_WF   = 166912;     // 768 f
constexpr int OFF_B0   = 169984;     // 256 f (prescaled by 30)
constexpr int OFF_B123 = 171008;     // 768 f (prescaled by 30)
constexpr int OFF_X    = 174080;     // 384 f
constexpr int OFF_PBUF = 175616;     // 1536 f (4 quarters x 128 rows x 3)
constexpr int SMEM_TOTAL = 181760;
}

// prepped weights: slab blob = [m][layer*16 + s] of 8KB, laid out as
// 4 o-quarters x 64 o-rows x 32B; row = 4 q-words (uint2):
//   {W(k=2q,2q+1), W(k=2q+8,2q+9)}  (fp16)
__device__ __align__(16) unsigned char g_wp[(size_t)Mexp * 48 * 8192];

// ---------------------------------------------------------------------------
__device__ __forceinline__ uint32_t smem_u32(const void* p) {
    uint32_t a;
    asm("{ .reg .u64 t; cvta.to.shared.u64 t, %1; cvt.u32.u64 %0, t; }" : "=r"(a) : "l"(p));
    return a;
}
__device__ __forceinline__ void cp16(uint32_t s, const void* g) {
    asm volatile("cp.async.cg.shared.global [%0], [%1], 16;" :: "r"(s), "l"(g));
}
__device__ __forceinline__ void cp_commit() { asm volatile("cp.async.commit_group;"); }
__device__ __forceinline__ void cp_wait0() {
    asm volatile("cp.async.wait_group 0;" ::: "memory");
}
__device__ __forceinline__ uint32_t pack2h(float v0, float v1) {
    __half2 t = __floats2half2_rn(v0, v1);
    return *reinterpret_cast<uint32_t*>(&t);
}
// A swizzled byte offset: row r (0..127), col k (0..255) fp16
__device__ __forceinline__ uint32_t aoff(int r, int k) {
    return (uint32_t)(r * 512 + ((((k >> 3) ^ (r & 7)) << 4) | ((k & 7) * 2)));
}
__device__ __forceinline__ void mma16816(float* d, const uint32_t* a,
                                         uint32_t b0, uint32_t b1) {
    asm volatile(
        "mma.sync.aligned.m16n8k16.row.col.f32.f16.f16.f32 "
        "{%0,%1,%2,%3}, {%4,%5,%6,%7}, {%8,%9}, {%0,%1,%2,%3};"
        : "+f"(d[0]), "+f"(d[1]), "+f"(d[2]), "+f"(d[3])
        : "r"(a[0]), "r"(a[1]), "r"(a[2]), "r"(a[3]), "r"(b0), "r"(b1));
}
__device__ __forceinline__ void ldsm4(uint32_t* r, uint32_t addr) {
    asm volatile("ldmatrix.sync.aligned.m8n8.x4.shared.b16 {%0,%1,%2,%3}, [%4];"
                 : "=r"(r[0]), "=r"(r[1]), "=r"(r[2]), "=r"(r[3]) : "r"(addr));
}

// ---------------------------------------------------------------------------
// Prep: fp32 W[m][o][i] -> k16-slab blobs (8KB), quarter-major, 32B rows.
// ---------------------------------------------------------------------------
__global__ void prep_weights(const float* __restrict__ w, int layer) {
    int id = blockIdx.x * blockDim.x + threadIdx.x;   // 262144
    int o = id & 255;
    int s = (id >> 8) & 15;
    int m = id >> 12;
    const float* src = w + ((size_t)m * 256 + o) * 256 + s * 16;
    unsigned char* dst = g_wp + (size_t)(m * 48 + layer * 16 + s) * 8192
                       + (o >> 6) * 2048 + (o & 63) * 32;
#pragma unroll
    for (int q = 0; q < 4; q++) {
        uint2 v;
        v.x = pack2h(src[2 * q],     src[2 * q + 1]);
        v.y = pack2h(src[2 * q + 8], src[2 * q + 9]);
        *reinterpret_cast<uint2*>(dst + q * 8) = v;
    }
}

// ---------------------------------------------------------------------------
// Main kernel. grid = Mexp*64 = 4096 CTAs (expert-major), 256 threads.
// ---------------------------------------------------------------------------
__global__ void __launch_bounds__(256, 1)
siren_mma(const float* __restrict__ x,
          const float* __restrict__ w0, const float* __restrict__ b0,
          const float* __restrict__ b1, const float* __restrict__ b2,
          const float* __restrict__ b3,
          const float* __restrict__ wf, const float* __restrict__ bf,
          float* __restrict__ out) {
    extern __shared__ __align__(16) unsigned char smem[];
    const uint32_t sb = smem_u32(smem);
    float* w0s  = reinterpret_cast<float*>(smem + OFF_W0);
    float* wfs  = reinterpret_cast<float*>(smem + OFF_WF);
    float* b0s  = reinterpret_cast<float*>(smem + OFF_B0);
    float* b123 = reinterpret_cast<float*>(smem + OFF_B123);
    float* xs   = reinterpret_cast<float*>(smem + OFF_X);
    float* pbuf = reinterpret_cast<float*>(smem + OFF_PBUF);

    const int tid  = threadIdx.x;
    const int lane = tid & 31;
    const int wid  = tid >> 5;
    const int wm   = wid & 1;          // m-half: rows wm*64..+63
    const int wnq  = wid >> 1;         // n-quarter: cols wnq*64..+63
    const int rl   = lane >> 2;        // 0..7
    const int q    = lane & 3;         // 0..3
    const int m    = blockIdx.x >> 6;
    const int bt   = blockIdx.x & 63;
    const int row0 = bt * 128;
    const int lrow  = lane & 15;
    const int lhalf = lane >> 4;

    const unsigned char* wpm = g_wp + (size_t)m * 48 * 8192;

    // ---- prefetch slab 0 (own n-quarter: 2KB, warp-private region) ----
    {
        uint32_t dst = sb + OFF_WBUF + (uint32_t)(wid * 2048 + lane * 64);
        const unsigned char* src = wpm + wnq * 2048 + lane * 64;
#pragma unroll
        for (int i = 0; i < 4; i++) cp16(dst + i * 16, src + i * 16);
        cp_commit();
    }

    // ---- stage small tensors (w0/b0/b123 prescaled by 30) ----
    for (int i = tid; i < 768; i += 256) w0s[i] = W0F * w0[m * 768 + i];
    for (int i = tid; i < 768; i += 256) wfs[i] = wf[m * 768 + i];
    if (tid < 256) {
        b0s[tid]        = W0F * b0[m * 256 + tid];
        b123[tid]       = W0F * b1[m * 256 + tid];
        b123[256 + tid] = W0F * b2[m * 256 + tid];
        b123[512 + tid] = W0F * b3[m * 256 + tid];
    }
    for (int i = tid; i < 384; i += 256) xs[i] = x[(size_t)row0 * 3 + i];
    __syncthreads();

    // ---- layer 0: writes A buffer 0 (128 rows x 256 cols) ----
    {
#pragma unroll 4
        for (int i = 0; i < 64; i++) {
            int pid = i * 256 + tid;
            int r = pid & 127;
            int c = (pid >> 7) * 2;
            float x0 = xs[r * 3], x1 = xs[r * 3 + 1], x2 = xs[r * 3 + 2];
            float p0 = fmaf(x2, w0s[c * 3 + 2], fmaf(x1, w0s[c * 3 + 1],
                       fmaf(x0, w0s[c * 3 + 0], b0s[c])));
            float p1 = fmaf(x2, w0s[c * 3 + 5], fmaf(x1, w0s[c * 3 + 4],
                       fmaf(x0, w0s[c * 3 + 3], b0s[c + 1])));
            float v0 = __sinf(p0);
            float v1 = __sinf(p1);
            *reinterpret_cast<uint32_t*>(smem + OFF_A + aoff(r, c)) = pack2h(v0, v1);
        }
    }
    __syncthreads();

    // ---- 3 hidden layers; A ping-pongs between buffers 0/1 ----
    int t = 0;
#pragma unroll 1
    for (int L = 0; L < 3; L++) {
        const uint32_t rbase = sb + OFF_A + (uint32_t)((L & 1) ? 65536 : 0);
        unsigned char* wptr  = smem + OFF_A + ((L & 1) ? 0 : 65536);

        float acc[8][4][4];               // [n][f][v]
#pragma unroll
        for (int n = 0; n < 8; n++)
#pragma unroll
            for (int f = 0; f < 4; f++)
#pragma unroll
                for (int v = 0; v < 4; v++) acc[n][f][v] = 0.0f;

        uint32_t ah[4][4];

#pragma unroll 1
        for (int s = 0; s < 16; s++, t++) {
            cp_wait0();
            __syncwarp();
            if (t < 47) {
                uint32_t dst = sb + OFF_WBUF + ((t + 1) & 1) * 16384
                             + (uint32_t)(wid * 2048 + lane * 64);
                const unsigned char* src = wpm + (size_t)(t + 1) * 8192
                                         + wnq * 2048 + lane * 64;
#pragma unroll
                for (int i = 0; i < 4; i++) cp16(dst + i * 16, src + i * 16);
                cp_commit();
            }
            const unsigned char* wb = smem + OFF_WBUF + (t & 1) * 16384 + wid * 2048;

            // B fragments: 8 x LDS.64 {W.x, W.y}, 32B rows (conflict-free)
            uint2 bq[8];
#pragma unroll
            for (int n = 0; n < 8; n++)
                bq[n] = *reinterpret_cast<const uint2*>(wb + (n * 8 + rl) * 32 + q * 8);

            // A fragments: f=0..3 via ldmatrix.x4 (warp's 64-row m-half)
            {
                int c3 = s * 2 + lhalf;
#pragma unroll
                for (int f = 0; f < 4; f++) {
                    int row = wm * 64 + f * 16 + lrow;
                    uint32_t ad = rbase + (uint32_t)(row * 512 + ((c3 ^ (row & 7)) << 4));
                    ldsm4(ah[f], ad);
                }
            }

            // single pass: A * W
#pragma unroll
            for (int n = 0; n < 8; n++)
#pragma unroll
                for (int f = 0; f < 4; f++)
                    mma16816(acc[n][f], ah[f], bq[n].x, bq[n].y);
        }

        // no post-mainloop barrier: epilogue writes the OTHER A buffer

        if (L < 2) {
            const float* bl = b123 + L * 256;
#pragma unroll
            for (int n = 0; n < 8; n++) {
#pragma unroll
                for (int f = 0; f < 4; f++) {
                    int r   = wm * 64 + f * 16 + rl;
                    int col = wnq * 64 + n * 8 + q * 2;
                    float bb0 = bl[col], bb1 = bl[col + 1];
                    float v0 = __sinf(fmaf(W0F, acc[n][f][0], bb0));
                    float v1 = __sinf(fmaf(W0F, acc[n][f][1], bb1));
                    float v2 = __sinf(fmaf(W0F, acc[n][f][2], bb0));
                    float v3 = __sinf(fmaf(W0F, acc[n][f][3], bb1));
                    *reinterpret_cast<uint32_t*>(wptr + aoff(r, col)) = pack2h(v0, v1);
                    *reinterpret_cast<uint32_t*>(wptr + aoff(r + 8, col)) = pack2h(v2, v3);
                }
            }
            __syncthreads();   // A writes visible before next-layer reads
        } else {
            // final: sine + wf dot (3 outputs), partial per n-quarter
            const float* bl = b123 + 512;
            float p[8][3];
#pragma unroll
            for (int i = 0; i < 8; i++)
#pragma unroll
                for (int o = 0; o < 3; o++) p[i][o] = 0.0f;
#pragma unroll
            for (int n = 0; n < 8; n++) {
#pragma unroll
                for (int f = 0; f < 4; f++) {
                    int col = wnq * 64 + n * 8 + q * 2;
                    float bb0 = bl[col], bb1 = bl[col + 1];
                    float v0 = __sinf(fmaf(W0F, acc[n][f][0], bb0));
                    float v1 = __sinf(fmaf(W0F, acc[n][f][1], bb1));
                    float v2 = __sinf(fmaf(W0F, acc[n][f][2], bb0));
                    float v3 = __sinf(fmaf(W0F, acc[n][f][3], bb1));
#pragma unroll
                    for (int o = 0; o < 3; o++) {
                        float wf0 = wfs[o * 256 + col], wf1 = wfs[o * 256 + col + 1];
                        p[f * 2 + 0][o] = fmaf(v0, wf0, fmaf(v1, wf1, p[f * 2 + 0][o]));
                        p[f * 2 + 1][o] = fmaf(v2, wf0, fmaf(v3, wf1, p[f * 2 + 1][o]));
                    }
                }
            }
#pragma unroll
            for (int i = 0; i < 8; i++)
#pragma unroll
                for (int o = 0; o < 3; o++) {
                    p[i][o] += __shfl_xor_sync(0xffffffffu, p[i][o], 1);
                    p[i][o] += __shfl_xor_sync(0xffffffffu, p[i][o], 2);
                }
            if (q == 0) {
#pragma unroll
                for (int f = 0; f < 4; f++)
#pragma unroll
                    for (int pr = 0; pr < 2; pr++) {
                        int r = wm * 64 + f * 16 + pr * 8 + rl;   // 0..127
#pragma unroll
                        for (int o = 0; o < 3; o++)
                            pbuf[wnq * 384 + r * 3 + o] = p[f * 2 + pr][o];
                    }
            }
            __syncthreads();
            for (int i = tid; i < 384; i += 256) {
                int r = i / 3, o = i - r * 3;
                float v = bf[m * 3 + o];
#pragma unroll
                for (int qq = 0; qq < 4; qq++) v += pbuf[qq * 384 + i];
                out[((size_t)(row0 + r) * Mexp + m) * 3 + o] = v;
            }
        }
    }
}

// ---------------------------------------------------------------------------
extern "C" void kernel_launch(void* const* d_in, const int* in_sizes, int n_in,
                              void* d_out, int out_size) {
    (void)in_sizes; (void)n_in; (void)out_size;
    const float* x  = (const float*)d_in[0];
    const float* w0 = (const float*)d_in[1];
    const float* b0 = (const float*)d_in[2];
    const float* w1 = (const float*)d_in[3];
    const float* b1 = (const float*)d_in[4];
    const float* w2 = (const float*)d_in[5];
    const float* b2 = (const float*)d_in[6];
    const float* w3 = (const float*)d_in[7];
    const float* b3 = (const float*)d_in[8];
    const float* wf = (const float*)d_in[9];
    const float* bf = (const float*)d_in[10];
    float* out = (float*)d_out;

    cudaFuncSetAttribute(siren_mma, cudaFuncAttributeMaxDynamicSharedMemorySize,
                         SMEM_TOTAL);

    prep_weights<<<1024, 256>>>(w1, 0);
    prep_weights<<<1024, 256>>>(w2, 1);
    prep_weights<<<1024, 256>>>(w3, 2);

    siren_mma<<<Mexp * (Bdim / 128), 256, SMEM_TOTAL>>>(
        x, w0, b0, b1, b2, b3, wf, bf, out);
}

// round 16
// speedup vs baseline: 1.2815x; 1.2815x over previous
#include <cuda_runtime.h>
#include <cuda_fp16.h>
#include <cstdint>

// ===========================================================================
// PackedSirenExperts via mma.sync m16n8k16 fp16 (portable PTX, compute_103).
// R16 = R14 (best: 656us — 8 warps, warp tile 64x32, warp-private B,
// A double-buffered, prescaled biases) + B staged through THREE rotating
// 8KB buffers with prefetch distance 2:
//   iter t: prefetch slab t+2 -> buf[(t+2)%3]; commit; wait_group 2
//   (group t guaranteed done; t+1/t+2 in flight) -> the ~250cyc L2 latency
//   of each cp.async is covered by ~2 slabs of MMA work instead of ~0.5.
// Single-pass fp16 MMA (rel_err ~6e-4). CTA = (expert, 64 rows), 256 thr;
// 2 CTAs/SM (~107 KB smem).
// ===========================================================================

namespace {
constexpr int Mexp = 64;
constexpr int Bdim = 8192;
constexpr float W0F = 30.0f;

constexpr int OFF_A    = 0;          // 2 x (64 rows x 512B swizzled fp16)
constexpr int OFF_WBUF = 65536;      // 3 x 8192 (triple-buffered k16 slab)
constexpr int OFF_W0   = 90112;      // 768 f (prescaled by 30)
constexpr int OFF_WF   = 93184;      // 768 f
constexpr int OFF_B0   = 96256;      // 256 f (prescaled by 30)
constexpr int OFF_B123 = 97280;      // 768 f (prescaled by 30)
constexpr int OFF_X    = 100352;     // 192 f
constexpr int OFF_PBUF = 101120;     // 1536 f
constexpr int SMEM_TOTAL = 107264;
}

// prepped weights: slab blob = [m][layer*16 + s] of 8KB, laid out as
// 8 o-eighths (wn) x 32 o-rows x 32B; row = 4 q-words (uint2):
//   {W(k=2q,2q+1), W(k=2q+8,2q+9)}  (fp16)
__device__ __align__(16) unsigned char g_wp[(size_t)Mexp * 48 * 8192];

// ---------------------------------------------------------------------------
__device__ __forceinline__ uint32_t smem_u32(const void* p) {
    uint32_t a;
    asm("{ .reg .u64 t; cvta.to.shared.u64 t, %1; cvt.u32.u64 %0, t; }" : "=r"(a) : "l"(p));
    return a;
}
__device__ __forceinline__ void cp16(uint32_t s, const void* g) {
    asm volatile("cp.async.cg.shared.global [%0], [%1], 16;" :: "r"(s), "l"(g));
}
__device__ __forceinline__ void cp_commit() { asm volatile("cp.async.commit_group;"); }
template <int N>
__device__ __forceinline__ void cp_wait() {
    asm volatile("cp.async.wait_group %0;" :: "n"(N) : "memory");
}
__device__ __forceinline__ uint32_t pack2h(float v0, float v1) {
    __half2 t = __floats2half2_rn(v0, v1);
    return *reinterpret_cast<uint32_t*>(&t);
}
// A swizzled byte offset: row r (0..63), col k (0..255) fp16
__device__ __forceinline__ uint32_t aoff(int r, int k) {
    return (uint32_t)(r * 512 + ((((k >> 3) ^ (r & 7)) << 4) | ((k & 7) * 2)));
}
__device__ __forceinline__ void mma16816(float* d, const uint32_t* a,
                                         uint32_t b0, uint32_t b1) {
    asm volatile(
        "mma.sync.aligned.m16n8k16.row.col.f32.f16.f16.f32 "
        "{%0,%1,%2,%3}, {%4,%5,%6,%7}, {%8,%9}, {%0,%1,%2,%3};"
        : "+f"(d[0]), "+f"(d[1]), "+f"(d[2]), "+f"(d[3])
        : "r"(a[0]), "r"(a[1]), "r"(a[2]), "r"(a[3]), "r"(b0), "r"(b1));
}
__device__ __forceinline__ void ldsm4(uint32_t* r, uint32_t addr) {
    asm volatile("ldmatrix.sync.aligned.m8n8.x4.shared.b16 {%0,%1,%2,%3}, [%4];"
                 : "=r"(r[0]), "=r"(r[1]), "=r"(r[2]), "=r"(r[3]) : "r"(addr));
}

// ---------------------------------------------------------------------------
// Prep: fp32 W[m][o][i] -> k16-slab blobs (8KB), eighth-major, 32B rows.
// ---------------------------------------------------------------------------
__global__ void prep_weights(const float* __restrict__ w, int layer) {
    int id = blockIdx.x * blockDim.x + threadIdx.x;   // 262144
    int o = id & 255;
    int s = (id >> 8) & 15;
    int m = id >> 12;
    const float* src = w + ((size_t)m * 256 + o) * 256 + s * 16;
    unsigned char* dst = g_wp + (size_t)(m * 48 + layer * 16 + s) * 8192
                       + (o >> 5) * 1024 + (o & 31) * 32;
#pragma unroll
    for (int q = 0; q < 4; q++) {
        uint2 v;
        v.x = pack2h(src[2 * q],     src[2 * q + 1]);
        v.y = pack2h(src[2 * q + 8], src[2 * q + 9]);
        *reinterpret_cast<uint2*>(dst + q * 8) = v;
    }
}

// ---------------------------------------------------------------------------
// Main kernel. grid = Mexp*128 = 8192 CTAs (expert-major), 256 threads.
// ---------------------------------------------------------------------------
__global__ void __launch_bounds__(256, 2)
siren_mma(const float* __restrict__ x,
          const float* __restrict__ w0, const float* __restrict__ b0,
          const float* __restrict__ b1, const float* __restrict__ b2,
          const float* __restrict__ b3,
          const float* __restrict__ wf, const float* __restrict__ bf,
          float* __restrict__ out) {
    extern __shared__ __align__(16) unsigned char smem[];
    const uint32_t sb = smem_u32(smem);
    float* w0s  = reinterpret_cast<float*>(smem + OFF_W0);
    float* wfs  = reinterpret_cast<float*>(smem + OFF_WF);
    float* b0s  = reinterpret_cast<float*>(smem + OFF_B0);
    float* b123 = reinterpret_cast<float*>(smem + OFF_B123);
    float* xs   = reinterpret_cast<float*>(smem + OFF_X);
    float* pbuf = reinterpret_cast<float*>(smem + OFF_PBUF);

    const int tid  = threadIdx.x;
    const int lane = tid & 31;
    const int wn   = tid >> 5;         // warp = n-eighth: cols wn*32..+31
    const int rl   = lane >> 2;        // 0..7
    const int q    = lane & 3;         // 0..3
    const int m    = blockIdx.x >> 7;
    const int bt   = blockIdx.x & 127;
    const int row0 = bt * 64;
    const int lrow  = lane & 15;
    const int lhalf = lane >> 4;

    const unsigned char* wpm = g_wp + (size_t)m * 48 * 8192;
    const uint32_t wpriv = (uint32_t)(wn * 1024 + lane * 16);

    // ---- prefetch slabs 0 and 1 (two commit groups) ----
    {
        uint32_t d0 = sb + OFF_WBUF + wpriv;
        const unsigned char* s0 = wpm + wpriv;
        cp16(d0, s0);
        cp16(d0 + 512, s0 + 512);
        cp_commit();
        uint32_t d1 = sb + OFF_WBUF + 8192 + wpriv;
        const unsigned char* s1 = wpm + 8192 + wpriv;
        cp16(d1, s1);
        cp16(d1 + 512, s1 + 512);
        cp_commit();
    }

    // ---- stage small tensors (w0/b0/b123 prescaled by 30) ----
    for (int i = tid; i < 768; i += 256) w0s[i] = W0F * w0[m * 768 + i];
    for (int i = tid; i < 768; i += 256) wfs[i] = wf[m * 768 + i];
    if (tid < 256) {
        b0s[tid]        = W0F * b0[m * 256 + tid];
        b123[tid]       = W0F * b1[m * 256 + tid];
        b123[256 + tid] = W0F * b2[m * 256 + tid];
        b123[512 + tid] = W0F * b3[m * 256 + tid];
    }
    if (tid < 192) xs[tid] = x[(size_t)row0 * 3 + tid];
    __syncthreads();

    // ---- layer 0: writes A buffer 0 ----
    {
#pragma unroll 4
        for (int i = 0; i < 32; i++) {
            int pid = i * 256 + tid;
            int r = pid & 63;
            int c = (pid >> 6) * 2;
            float x0 = xs[r * 3], x1 = xs[r * 3 + 1], x2 = xs[r * 3 + 2];
            float p0 = fmaf(x2, w0s[c * 3 + 2], fmaf(x1, w0s[c * 3 + 1],
                       fmaf(x0, w0s[c * 3 + 0], b0s[c])));
            float p1 = fmaf(x2, w0s[c * 3 + 5], fmaf(x1, w0s[c * 3 + 4],
                       fmaf(x0, w0s[c * 3 + 3], b0s[c + 1])));
            float v0 = __sinf(p0);
            float v1 = __sinf(p1);
            *reinterpret_cast<uint32_t*>(smem + OFF_A + aoff(r, c)) = pack2h(v0, v1);
        }
    }
    __syncthreads();

    // ---- 3 hidden layers; A ping-pongs; B rotates through 3 buffers ----
    int t = 0;
    int ib = 0;                         // read buffer index = t % 3
#pragma unroll 1
    for (int L = 0; L < 3; L++) {
        const uint32_t rbase = sb + OFF_A + (uint32_t)((L & 1) ? 32768 : 0);
        unsigned char* wptr  = smem + OFF_A + ((L & 1) ? 0 : 32768);

        float acc[4][4][4];               // [n][f][v]
#pragma unroll
        for (int n = 0; n < 4; n++)
#pragma unroll
            for (int f = 0; f < 4; f++)
#pragma unroll
                for (int v = 0; v < 4; v++) acc[n][f][v] = 0.0f;

        uint32_t ah[4][4];

#pragma unroll 1
        for (int s = 0; s < 16; s++, t++) {
            // prefetch slab t+2 into buffer (ib+2)%3, then wait for group t
            if (t < 46) {
                int iw = ib + 2; if (iw >= 3) iw -= 3;
                uint32_t dst = sb + OFF_WBUF + (uint32_t)(iw * 8192) + wpriv;
                const unsigned char* src = wpm + (size_t)(t + 2) * 8192 + wpriv;
                cp16(dst, src);
                cp16(dst + 512, src + 512);
                cp_commit();
                cp_wait<2>();
            } else if (t == 46) {
                cp_wait<1>();
            } else {
                cp_wait<0>();
            }
            __syncwarp();
            const unsigned char* wb = smem + OFF_WBUF + ib * 8192 + wn * 1024;

            // B fragments: 4 x LDS.64 {W.x, W.y}, 32B rows (conflict-free)
            uint2 bq[4];
#pragma unroll
            for (int n = 0; n < 4; n++)
                bq[n] = *reinterpret_cast<const uint2*>(wb + (n * 8 + rl) * 32 + q * 8);

            // A fragments: f=0..3 via ldmatrix.x4 (from read buffer)
            {
                int c3 = s * 2 + lhalf;
#pragma unroll
                for (int f = 0; f < 4; f++) {
                    int row = f * 16 + lrow;
                    uint32_t ad = rbase + (uint32_t)(row * 512 + ((c3 ^ (row & 7)) << 4));
                    ldsm4(ah[f], ad);
                }
            }

            // single pass: A * W
#pragma unroll
            for (int n = 0; n < 4; n++)
#pragma unroll
                for (int f = 0; f < 4; f++)
                    mma16816(acc[n][f], ah[f], bq[n].x, bq[n].y);

            if (++ib >= 3) ib = 0;
        }

        // no post-mainloop barrier: epilogue writes the OTHER A buffer

        if (L < 2) {
            const float* bl = b123 + L * 256;
#pragma unroll
            for (int n = 0; n < 4; n++) {
#pragma unroll
                for (int f = 0; f < 4; f++) {
                    int r   = f * 16 + rl;
                    int col = wn * 32 + n * 8 + q * 2;
                    float bb0 = bl[col], bb1 = bl[col + 1];
                    float v0 = __sinf(fmaf(W0F, acc[n][f][0], bb0));
                    float v1 = __sinf(fmaf(W0F, acc[n][f][1], bb1));
                    float v2 = __sinf(fmaf(W0F, acc[n][f][2], bb0));
                    float v3 = __sinf(fmaf(W0F, acc[n][f][3], bb1));
                    *reinterpret_cast<uint32_t*>(wptr + aoff(r, col)) = pack2h(v0, v1);
                    *reinterpret_cast<uint32_t*>(wptr + aoff(r + 8, col)) = pack2h(v2, v3);
                }
            }
            __syncthreads();   // A writes visible before next-layer reads
        } else {
            // final: sine + wf dot (3 outputs), partial per n-eighth
            const float* bl = b123 + 512;
            float p[8][3];
#pragma unroll
            for (int i = 0; i < 8; i++)
#pragma unroll
                for (int o = 0; o < 3; o++) p[i][o] = 0.0f;
#pragma unroll
            for (int n = 0; n < 4; n++) {
#pragma unroll
                for (int f = 0; f < 4; f++) {
                    int col = wn * 32 + n * 8 + q * 2;
                    float bb0 = bl[col], bb1 = bl[col + 1];
                    float v0 = __sinf(fmaf(W0F, acc[n][f][0], bb0));
                    float v1 = __sinf(fmaf(W0F, acc[n][f][1], bb1));
                    float v2 = __sinf(fmaf(W0F, acc[n][f][2], bb0));
                    float v3 = __sinf(fmaf(W0F, acc[n][f][3], bb1));
#pragma unroll
                    for (int o = 0; o < 3; o++) {
                        float wf0 = wfs[o * 256 + col], wf1 = wfs[o * 256 + col + 1];
                        p[f * 2 + 0][o] = fmaf(v0, wf0, fmaf(v1, wf1, p[f * 2 + 0][o]));
                        p[f * 2 + 1][o] = fmaf(v2, wf0, fmaf(v3, wf1, p[f * 2 + 1][o]));
                    }
                }
            }
#pragma unroll
            for (int i = 0; i < 8; i++)
#pragma unroll
                for (int o = 0; o < 3; o++) {
                    p[i][o] += __shfl_xor_sync(0xffffffffu, p[i][o], 1);
                    p[i][o] += __shfl_xor_sync(0xffffffffu, p[i][o], 2);
                }
            if (q == 0) {
#pragma unroll
                for (int f = 0; f < 4; f++)
#pragma unroll
                    for (int pr = 0; pr < 2; pr++) {
                        int r = f * 16 + pr * 8 + rl;   // 0..63
#pragma unroll
                        for (int o = 0; o < 3; o++)
                            pbuf[wn * 192 + r * 3 + o] = p[f * 2 + pr][o];
                    }
            }
            __syncthreads();
            if (tid < 192) {
                int r = tid / 3, o = tid - r * 3;
                float v = bf[m * 3 + o];
#pragma unroll
                for (int w8 = 0; w8 < 8; w8++) v += pbuf[w8 * 192 + tid];
                out[((size_t)(row0 + r) * Mexp + m) * 3 + o] = v;
            }
        }
    }
}

// ---------------------------------------------------------------------------
extern "C" void kernel_launch(void* const* d_in, const int* in_sizes, int n_in,
                              void* d_out, int out_size) {
    (void)in_sizes; (void)n_in; (void)out_size;
    const float* x  = (const float*)d_in[0];
    const float* w0 = (const float*)d_in[1];
    const float* b0 = (const float*)d_in[2];
    const float* w1 = (const float*)d_in[3];
    const float* b1 = (const float*)d_in[4];
    const float* w2 = (const float*)d_in[5];
    const float* b2 = (const float*)d_in[6];
    const float* w3 = (const float*)d_in[7];
    const float* b3 = (const float*)d_in[8];
    const float* wf = (const float*)d_in[9];
    const float* bf = (const float*)d_in[10];
    float* out = (float*)d_out;

    cudaFuncSetAttribute(siren_mma, cudaFuncAttributeMaxDynamicSharedMemorySize,
                         SMEM_TOTAL);

    prep_weights<<<1024, 256>>>(w1, 0);
    prep_weights<<<1024, 256>>>(w2, 1);
    prep_weights<<<1024, 256>>>(w3, 2);

    siren_mma<<<Mexp * (Bdim / 64), 256, SMEM_TOTAL>>>(
        x, w0, b0, b1, b2, b3, wf, bf, out);
}

// round 17
// speedup vs baseline: 1.2977x; 1.0127x over previous
#include <cuda_runtime.h>
#include <cuda_fp16.h>
#include <cstdint>

// ===========================================================================
// PackedSirenExperts via mma.sync m16n8k16 fp16 (portable PTX, compute_103).
// R17 = R16 (647us) + overhead polish:
//   - FOUR B buffers, id = t&3 = s&3 (16%4==0) + unroll-4 slab loop ->
//     all buffer addressing constant-folded (alu cut). Distance-2 wait.
//   - pbuf aliased into the dead A write-buffer in the final layer ->
//     fits 2 CTAs/SM (109.3 KB each).
//   - single merged prep kernel (one launch instead of three).
// Single-pass fp16 MMA (rel_err ~6e-4), 8 warps, warp tile 64x32,
// warp-private B staging, A double-buffered, prescaled biases.
// CTA = (expert, 64 rows), 256 thr; 2 CTAs/SM.
// ===========================================================================

namespace {
constexpr int Mexp = 64;
constexpr int Bdim = 8192;
constexpr float W0F = 30.0f;

constexpr int OFF_A    = 0;          // 2 x (64 rows x 512B swizzled fp16)
constexpr int OFF_WBUF = 65536;      // 4 x 8192 (quad-buffered k16 slab)
constexpr int OFF_W0   = 98304;      // 768 f (prescaled by 30)
constexpr int OFF_WF   = 101376;     // 768 f
constexpr int OFF_B0   = 104448;     // 256 f (prescaled by 30)
constexpr int OFF_B123 = 105472;     // 768 f (prescaled by 30)
constexpr int OFF_X    = 108544;     // 192 f
constexpr int SMEM_TOTAL = 109312;
// pbuf (final layer only) aliases the dead A write-buffer: OFF_A + 32768
constexpr int OFF_PBUF = OFF_A + 32768;
}

// prepped weights: slab blob = [m][layer*16 + s] of 8KB, laid out as
// 8 o-eighths (wn) x 32 o-rows x 32B; row = 4 q-words (uint2):
//   {W(k=2q,2q+1), W(k=2q+8,2q+9)}  (fp16)
__device__ __align__(16) unsigned char g_wp[(size_t)Mexp * 48 * 8192];

// ---------------------------------------------------------------------------
__device__ __forceinline__ uint32_t smem_u32(const void* p) {
    uint32_t a;
    asm("{ .reg .u64 t; cvta.to.shared.u64 t, %1; cvt.u32.u64 %0, t; }" : "=r"(a) : "l"(p));
    return a;
}
__device__ __forceinline__ void cp16(uint32_t s, const void* g) {
    asm volatile("cp.async.cg.shared.global [%0], [%1], 16;" :: "r"(s), "l"(g));
}
__device__ __forceinline__ void cp_commit() { asm volatile("cp.async.commit_group;"); }
template <int N>
__device__ __forceinline__ void cp_wait() {
    asm volatile("cp.async.wait_group %0;" :: "n"(N) : "memory");
}
__device__ __forceinline__ uint32_t pack2h(float v0, float v1) {
    __half2 t = __floats2half2_rn(v0, v1);
    return *reinterpret_cast<uint32_t*>(&t);
}
// A swizzled byte offset: row r (0..63), col k (0..255) fp16
__device__ __forceinline__ uint32_t aoff(int r, int k) {
    return (uint32_t)(r * 512 + ((((k >> 3) ^ (r & 7)) << 4) | ((k & 7) * 2)));
}
__device__ __forceinline__ void mma16816(float* d, const uint32_t* a,
                                         uint32_t b0, uint32_t b1) {
    asm volatile(
        "mma.sync.aligned.m16n8k16.row.col.f32.f16.f16.f32 "
        "{%0,%1,%2,%3}, {%4,%5,%6,%7}, {%8,%9}, {%0,%1,%2,%3};"
        : "+f"(d[0]), "+f"(d[1]), "+f"(d[2]), "+f"(d[3])
        : "r"(a[0]), "r"(a[1]), "r"(a[2]), "r"(a[3]), "r"(b0), "r"(b1));
}
__device__ __forceinline__ void ldsm4(uint32_t* r, uint32_t addr) {
    asm volatile("ldmatrix.sync.aligned.m8n8.x4.shared.b16 {%0,%1,%2,%3}, [%4];"
                 : "=r"(r[0]), "=r"(r[1]), "=r"(r[2]), "=r"(r[3]) : "r"(addr));
}

// ---------------------------------------------------------------------------
// Prep (single launch, all 3 layers): fp32 W[m][o][i] -> k16-slab blobs.
// ---------------------------------------------------------------------------
__global__ void prep_weights_all(const float* __restrict__ w1,
                                 const float* __restrict__ w2,
                                 const float* __restrict__ w3) {
    int id = blockIdx.x * blockDim.x + threadIdx.x;   // 786432
    int layer = id >> 18;
    int lid = id & 262143;
    int o = lid & 255;
    int s = (lid >> 8) & 15;
    int m = lid >> 12;
    const float* w = (layer == 0) ? w1 : (layer == 1) ? w2 : w3;
    const float* src = w + ((size_t)m * 256 + o) * 256 + s * 16;
    unsigned char* dst = g_wp + (size_t)(m * 48 + layer * 16 + s) * 8192
                       + (o >> 5) * 1024 + (o & 31) * 32;
#pragma unroll
    for (int q = 0; q < 4; q++) {
        uint2 v;
        v.x = pack2h(src[2 * q],     src[2 * q + 1]);
        v.y = pack2h(src[2 * q + 8], src[2 * q + 9]);
        *reinterpret_cast<uint2*>(dst + q * 8) = v;
    }
}

// ---------------------------------------------------------------------------
// Main kernel. grid = Mexp*128 = 8192 CTAs (expert-major), 256 threads.
// ---------------------------------------------------------------------------
__global__ void __launch_bounds__(256, 2)
siren_mma(const float* __restrict__ x,
          const float* __restrict__ w0, const float* __restrict__ b0,
          const float* __restrict__ b1, const float* __restrict__ b2,
          const float* __restrict__ b3,
          const float* __restrict__ wf, const float* __restrict__ bf,
          float* __restrict__ out) {
    extern __shared__ __align__(16) unsigned char smem[];
    const uint32_t sb = smem_u32(smem);
    float* w0s  = reinterpret_cast<float*>(smem + OFF_W0);
    float* wfs  = reinterpret_cast<float*>(smem + OFF_WF);
    float* b0s  = reinterpret_cast<float*>(smem + OFF_B0);
    float* b123 = reinterpret_cast<float*>(smem + OFF_B123);
    float* xs   = reinterpret_cast<float*>(smem + OFF_X);
    float* pbuf = reinterpret_cast<float*>(smem + OFF_PBUF);  // final layer only

    const int tid  = threadIdx.x;
    const int lane = tid & 31;
    const int wn   = tid >> 5;         // warp = n-eighth: cols wn*32..+31
    const int rl   = lane >> 2;        // 0..7
    const int q    = lane & 3;         // 0..3
    const int m    = blockIdx.x >> 7;
    const int bt   = blockIdx.x & 127;
    const int row0 = bt * 64;
    const int lrow  = lane & 15;
    const int lhalf = lane >> 4;

    const uint32_t wpriv = (uint32_t)(wn * 1024 + lane * 16);
    const unsigned char* wsrc = g_wp + (size_t)m * 48 * 8192 + wpriv;  // advances +8192/slab
    const uint32_t wdst = sb + OFF_WBUF + wpriv;

    // ---- prefetch slabs 0 and 1 (two commit groups) ----
    {
        cp16(wdst, wsrc);
        cp16(wdst + 512, wsrc + 512);
        cp_commit();
        cp16(wdst + 8192, wsrc + 8192);
        cp16(wdst + 8192 + 512, wsrc + 8192 + 512);
        cp_commit();
    }

    // ---- stage small tensors (w0/b0/b123 prescaled by 30) ----
    for (int i = tid; i < 768; i += 256) w0s[i] = W0F * w0[m * 768 + i];
    for (int i = tid; i < 768; i += 256) wfs[i] = wf[m * 768 + i];
    {
        b0s[tid]        = W0F * b0[m * 256 + tid];
        b123[tid]       = W0F * b1[m * 256 + tid];
        b123[256 + tid] = W0F * b2[m * 256 + tid];
        b123[512 + tid] = W0F * b3[m * 256 + tid];
    }
    if (tid < 192) xs[tid] = x[(size_t)row0 * 3 + tid];
    __syncthreads();

    // ---- layer 0: writes A buffer 0 ----
    {
#pragma unroll 4
        for (int i = 0; i < 32; i++) {
            int pid = i * 256 + tid;
            int r = pid & 63;
            int c = (pid >> 6) * 2;
            float x0 = xs[r * 3], x1 = xs[r * 3 + 1], x2 = xs[r * 3 + 2];
            float p0 = fmaf(x2, w0s[c * 3 + 2], fmaf(x1, w0s[c * 3 + 1],
                       fmaf(x0, w0s[c * 3 + 0], b0s[c])));
            float p1 = fmaf(x2, w0s[c * 3 + 5], fmaf(x1, w0s[c * 3 + 4],
                       fmaf(x0, w0s[c * 3 + 3], b0s[c + 1])));
            float v0 = __sinf(p0);
            float v1 = __sinf(p1);
            *reinterpret_cast<uint32_t*>(smem + OFF_A + aoff(r, c)) = pack2h(v0, v1);
        }
    }
    __syncthreads();

    // ---- 3 hidden layers; A ping-pongs; B rotates through 4 buffers ----
    int t = 0;
#pragma unroll 1
    for (int L = 0; L < 3; L++) {
        const uint32_t rbase = sb + OFF_A + (uint32_t)((L & 1) ? 32768 : 0);
        unsigned char* wptr  = smem + OFF_A + ((L & 1) ? 0 : 32768);

        float acc[4][4][4];               // [n][f][v]
#pragma unroll
        for (int n = 0; n < 4; n++)
#pragma unroll
            for (int f = 0; f < 4; f++)
#pragma unroll
                for (int v = 0; v < 4; v++) acc[n][f][v] = 0.0f;

        uint32_t ah[4][4];

#pragma unroll 4
        for (int s = 0; s < 16; s++, t++) {
            // prefetch slab t+2 into buffer (s+2)&3 (t&3 == s&3), wait group t
            if (t < 46) {
                uint32_t dst = wdst + (uint32_t)(((s + 2) & 3) * 8192);
                const unsigned char* src = wsrc + (size_t)(t + 2) * 8192;
                cp16(dst, src);
                cp16(dst + 512, src + 512);
                cp_commit();
                cp_wait<2>();
            } else if (t == 46) {
                cp_wait<1>();
            } else {
                cp_wait<0>();
            }
            __syncwarp();
            const unsigned char* wb = smem + OFF_WBUF + (s & 3) * 8192 + wn * 1024;

            // B fragments: 4 x LDS.64 {W.x, W.y}, 32B rows (conflict-free)
            uint2 bq[4];
#pragma unroll
            for (int n = 0; n < 4; n++)
                bq[n] = *reinterpret_cast<const uint2*>(wb + (n * 8 + rl) * 32 + q * 8);

            // A fragments: f=0..3 via ldmatrix.x4 (from read buffer)
            {
                int c3 = s * 2 + lhalf;
#pragma unroll
                for (int f = 0; f < 4; f++) {
                    int row = f * 16 + lrow;
                    uint32_t ad = rbase + (uint32_t)(row * 512 + ((c3 ^ (row & 7)) << 4));
                    ldsm4(ah[f], ad);
                }
            }

            // single pass: A * W
#pragma unroll
            for (int n = 0; n < 4; n++)
#pragma unroll
                for (int f = 0; f < 4; f++)
                    mma16816(acc[n][f], ah[f], bq[n].x, bq[n].y);
        }

        // no post-mainloop barrier: epilogue writes the OTHER A buffer

        if (L < 2) {
            const float* bl = b123 + L * 256;
#pragma unroll
            for (int n = 0; n < 4; n++) {
#pragma unroll
                for (int f = 0; f < 4; f++) {
                    int r   = f * 16 + rl;
                    int col = wn * 32 + n * 8 + q * 2;
                    float bb0 = bl[col], bb1 = bl[col + 1];
                    float v0 = __sinf(fmaf(W0F, acc[n][f][0], bb0));
                    float v1 = __sinf(fmaf(W0F, acc[n][f][1], bb1));
                    float v2 = __sinf(fmaf(W0F, acc[n][f][2], bb0));
                    float v3 = __sinf(fmaf(W0F, acc[n][f][3], bb1));
                    *reinterpret_cast<uint32_t*>(wptr + aoff(r, col)) = pack2h(v0, v1);
                    *reinterpret_cast<uint32_t*>(wptr + aoff(r + 8, col)) = pack2h(v2, v3);
                }
            }
            __syncthreads();   // A writes visible before next-layer reads
        } else {
            // final: sine + wf dot (3 outputs), partial per n-eighth.
            // pbuf aliases A buffer 1 (the dead write buffer for L=2; all
            // L=2 reads come from buffer 0, so no cross-warp hazard).
            const float* bl = b123 + 512;
            float p[8][3];
#pragma unroll
            for (int i = 0; i < 8; i++)
#pragma unroll
                for (int o = 0; o < 3; o++) p[i][o] = 0.0f;
#pragma unroll
            for (int n = 0; n < 4; n++) {
#pragma unroll
                for (int f = 0; f < 4; f++) {
                    int col = wn * 32 + n * 8 + q * 2;
                    float bb0 = bl[col], bb1 = bl[col + 1];
                    float v0 = __sinf(fmaf(W0F, acc[n][f][0], bb0));
                    float v1 = __sinf(fmaf(W0F, acc[n][f][1], bb1));
                    float v2 = __sinf(fmaf(W0F, acc[n][f][2], bb0));
                    float v3 = __sinf(fmaf(W0F, acc[n][f][3], bb1));
#pragma unroll
                    for (int o = 0; o < 3; o++) {
                        float wf0 = wfs[o * 256 + col], wf1 = wfs[o * 256 + col + 1];
                        p[f * 2 + 0][o] = fmaf(v0, wf0, fmaf(v1, wf1, p[f * 2 + 0][o]));
                        p[f * 2 + 1][o] = fmaf(v2, wf0, fmaf(v3, wf1, p[f * 2 + 1][o]));
                    }
                }
            }
#pragma unroll
            for (int i = 0; i < 8; i++)
#pragma unroll
                for (int o = 0; o < 3; o++) {
                    p[i][o] += __shfl_xor_sync(0xffffffffu, p[i][o], 1);
                    p[i][o] += __shfl_xor_sync(0xffffffffu, p[i][o], 2);
                }
            if (q == 0) {
#pragma unroll
                for (int f = 0; f < 4; f++)
#pragma unroll
                    for (int pr = 0; pr < 2; pr++) {
                        int r = f * 16 + pr * 8 + rl;   // 0..63
#pragma unroll
                        for (int o = 0; o < 3; o++)
                            pbuf[wn * 192 + r * 3 + o] = p[f * 2 + pr][o];
                    }
            }
            __syncthreads();
            if (tid < 192) {
                int r = tid / 3, o = tid - r * 3;
                float v = bf[m * 3 + o];
#pragma unroll
                for (int w8 = 0; w8 < 8; w8++) v += pbuf[w8 * 192 + tid];
                out[((size_t)(row0 + r) * Mexp + m) * 3 + o] = v;
            }
        }
    }
}

// ---------------------------------------------------------------------------
extern "C" void kernel_launch(void* const* d_in, const int* in_sizes, int n_in,
                              void* d_out, int out_size) {
    (void)in_sizes; (void)n_in; (void)out_size;
    const float* x  = (const float*)d_in[0];
    const float* w0 = (const float*)d_in[1];
    const float* b0 = (const float*)d_in[2];
    const float* w1 = (const float*)d_in[3];
    const float* b1 = (const float*)d_in[4];
    const float* w2 = (const float*)d_in[5];
    const float* b2 = (const float*)d_in[6];
    const float* w3 = (const float*)d_in[7];
    const float* b3 = (const float*)d_in[8];
    const float* wf = (const float*)d_in[9];
    const float* bf = (const float*)d_in[10];
    float* out = (float*)d_out;

    cudaFuncSetAttribute(siren_mma, cudaFuncAttributeMaxDynamicSharedMemorySize,
                         SMEM_TOTAL);

    prep_weights_all<<<3072, 256>>>(w1, w2, w3);

    siren_mma<<<Mexp * (Bdim / 64), 256, SMEM_TOTAL>>>(
        x, w0, b0, b1, b2, b3, wf, bf, out);
}